// round 17
// baseline (speedup 1.0000x reference)
#include <cuda_runtime.h>
#include <cuda_fp16.h>
#include <math.h>
#include <stdint.h>

#define BSZ 1024
#define SLOTS 74   // 148-CTA persistent grid, 74 slots per N-half

// ---------------------------------------------------------------------------
// Global scratch (static __device__ arrays, allocation-free)
// ---------------------------------------------------------------------------
__device__ float g_ctb[BSZ * 256];              // b0 + temb @ W0[6:134]
__device__ __half g_peWsh[256 * 256];           // roll-avg(pe) @ W0[2:6], fp16
__device__ __half g_h1[(size_t)BSZ * 256 * 256];
__device__ __half g_h2[(size_t)BSZ * 256 * 256];
__device__ __half g_W[2 * 256 * 256];           // W^T fp16, [l][n][k]
__device__ unsigned int g_bar;                  // monotonic global barrier ctr

// ---------------------------------------------------------------------------
// PTX helpers (sm_75/80-era: valid on the harness's sm_103 target)
// ---------------------------------------------------------------------------
__device__ __forceinline__ uint32_t s2u(const void* p) {
    uint32_t a;
    asm("{ .reg .u64 t; cvta.to.shared.u64 t, %1; cvt.u32.u64 %0, t; }"
        : "=r"(a) : "l"(p));
    return a;
}
#define CP_ASYNC16(dst, src) \
    asm volatile("cp.async.cg.shared.global [%0], [%1], 16;" :: "r"(dst), "l"(src))
#define CP_COMMIT() asm volatile("cp.async.commit_group;" ::: "memory")
#define CP_WAIT(n)  asm volatile("cp.async.wait_group %0;" :: "n"(n) : "memory")

__device__ __forceinline__ void ldsm4(uint32_t& r0, uint32_t& r1, uint32_t& r2,
                                      uint32_t& r3, uint32_t a) {
    asm volatile("ldmatrix.sync.aligned.m8n8.x4.shared.b16 {%0,%1,%2,%3}, [%4];"
                 : "=r"(r0), "=r"(r1), "=r"(r2), "=r"(r3) : "r"(a));
}
// fp16-accumulate HMMA (probe: expected rt=4 vs f32-acc rt=8)
__device__ __forceinline__ void mma16816h(uint32_t* d, const uint32_t* a,
                                          uint32_t b0, uint32_t b1) {
    asm volatile(
        "mma.sync.aligned.m16n8k16.row.col.f16.f16.f16.f16 "
        "{%0,%1}, {%2,%3,%4,%5}, {%6,%7}, {%0,%1};"
        : "+r"(d[0]), "+r"(d[1])
        : "r"(a[0]), "r"(a[1]), "r"(a[2]), "r"(a[3]), "r"(b0), "r"(b1));
}
// silu via single-MUFU tanh.approx: x*sigmoid(x) = 0.5x*tanh(0.5x) + 0.5x
__device__ __forceinline__ float fsilu(float x) {
    float t, h = 0.5f * x;
    asm("tanh.approx.f32 %0, %1;" : "=f"(t) : "f"(h));
    return fmaf(h, t, h);
}

// ---------------------------------------------------------------------------
// Kernel: merged prep (unchanged from R16 — validated).
// ---------------------------------------------------------------------------
__global__ void __launch_bounds__(256) k_prep(
    const float* __restrict__ W1, const float* __restrict__ W2,
    const float* __restrict__ W0, const float* __restrict__ t,
    const float* __restrict__ tw, const float* __restrict__ tb,
    const float* __restrict__ b0) {
    int bb = blockIdx.x, tid = threadIdx.x;
    if (bb < 128) {
        __shared__ float ts[32][33];
        int l = bb >> 6, tile = bb & 63;
        int kt = tile >> 3, nt = tile & 7;
        int tc = tid & 31, tr = tid >> 5;
        const float* W = l ? W2 : W1;
#pragma unroll
        for (int q = 0; q < 4; q++) {
            int r = tr + q * 8;
            ts[r][tc] = W[(kt * 32 + r) * 256 + nt * 32 + tc];
        }
        __syncthreads();
#pragma unroll
        for (int q = 0; q < 4; q++) {
            int r = tr + q * 8;
            g_W[l * 65536 + (nt * 32 + r) * 256 + kt * 32 + tc] =
                __float2half(ts[tc][r]);
        }
        return;
    }
    if (bb < 384) {
        int v = bb - 128, j = tid;
        const float dth = 6.283185307179586f / 256.0f;
        float f1 = (1.0f + 2.0f * __cosf(dth)) / 3.0f;
        float f2 = (1.0f + 2.0f * __cosf(2.0f * dth)) / 3.0f;
        float th = dth * (float)v;
        float s1 = __sinf(th), c1 = __cosf(th);
        float s2 = __sinf(2.0f * th), c2 = __cosf(2.0f * th);
        g_peWsh[v * 256 + j] = __float2half(
            f1 * (s1 * W0[2 * 256 + j] + c1 * W0[3 * 256 + j]) +
            f2 * (s2 * W0[4 * 256 + j] + c2 * W0[5 * 256 + j]));
        return;
    }
    int b = bb - 384;
    __shared__ float emb[128];
    __shared__ float tp[2][128];
    __shared__ float te[128];
    if (tid < 64) {
        float fr = expf(-9.210340371976184f * (float)tid / 63.0f);
        float a = t[b] * fr;
        emb[tid]      = sinf(a);
        emb[tid + 64] = cosf(a);
    }
    __syncthreads();
    {
        int j = tid & 127, hf = tid >> 7;
        const float* twp = tw + (hf * 64) * 128 + j;
        const float* ep  = emb + hf * 64;
        float a0 = 0.f, a1 = 0.f, a2 = 0.f, a3 = 0.f;
#pragma unroll 8
        for (int i = 0; i < 64; i += 4) {
            a0 += ep[i]     * twp[i * 128];
            a1 += ep[i + 1] * twp[(i + 1) * 128];
            a2 += ep[i + 2] * twp[(i + 2) * 128];
            a3 += ep[i + 3] * twp[(i + 3) * 128];
        }
        tp[hf][j] = (a0 + a1) + (a2 + a3);
    }
    __syncthreads();
    if (tid < 128) {
        float acc = tb[tid] + tp[0][tid] + tp[1][tid];
        te[tid] = acc / (1.0f + expf(-acc));
    }
    __syncthreads();
    {
        const float* wp = W0 + 6 * 256 + tid;
        float a0 = 0.f, a1 = 0.f, a2 = 0.f, a3 = 0.f;
#pragma unroll 8
        for (int k = 0; k < 128; k += 4) {
            a0 += te[k]     * wp[k * 256];
            a1 += te[k + 1] * wp[(k + 1) * 256];
            a2 += te[k + 2] * wp[(k + 2) * 256];
            a3 += te[k + 3] * wp[(k + 3) * 256];
        }
        g_ctb[b * 256 + tid] = b0[tid] + (a0 + a1) + (a2 + a3);
    }
}

// ---------------------------------------------------------------------------
// Kernel: layer 0 (unchanged from R16 — validated).
// ---------------------------------------------------------------------------
__global__ void __launch_bounds__(256) k_layer0(const float* __restrict__ x,
                                                const float* __restrict__ W0) {
    __shared__ float xs[512];
    __shared__ float xa[256], ya[256];
    __shared__ __half pws[66 * 256];
    int b = blockIdx.x >> 2, vq = blockIdx.x & 3;
    int tid = threadIdx.x;
    int v0q = vq * 64;
    {
        uint32_t pb = s2u(pws);
        const char* src = (const char*)g_peWsh;
        int base = (v0q + 255) & 255;
#pragma unroll
        for (int i = tid; i < 66 * 32; i += 256) {
            int row = i >> 5, seg = i & 31;
            int vsrc = (base + row) & 255;
            CP_ASYNC16(pb + row * 512 + seg * 16, src + vsrc * 512 + seg * 16);
        }
        CP_COMMIT();
    }
    for (int i = tid; i < 512; i += 256) xs[i] = x[b * 512 + i];
    __syncthreads();
    {
        int v = tid, vm = (v + 255) & 255, vp = (v + 1) & 255;
        xa[v] = (xs[2 * vm] + xs[2 * v] + xs[2 * vp]) * (1.0f / 3.0f);
        ya[v] = (xs[2 * vm + 1] + xs[2 * v + 1] + xs[2 * vp + 1]) * (1.0f / 3.0f);
    }
    CP_WAIT(0);
    __syncthreads();

    int cp = tid & 127, vg = tid >> 7, c0 = 2 * cp;
    float w00 = W0[c0], w01 = W0[c0 + 1];
    float w10 = W0[256 + c0], w11 = W0[256 + c0 + 1];
    float cb0 = g_ctb[b * 256 + c0], cb1 = g_ctb[b * 256 + c0 + 1];
    int j0 = vg * 32 + 1;

#define HEVAL(JJ, H0, H1)                                                  \
    do {                                                                   \
        int _j = (JJ);                                                     \
        float2 pw = __half22float2(*(const __half2*)(pws + _j * 256 + c0));\
        int _v = (v0q + _j - 1) & 255;                                     \
        float _xv = xa[_v], _yv = ya[_v];                                  \
        float a0 = fmaf(_xv, w00, fmaf(_yv, w10, pw.x + cb0));             \
        float a1 = fmaf(_xv, w01, fmaf(_yv, w11, pw.y + cb1));             \
        H0 = fsilu(a0); H1 = fsilu(a1);                                    \
    } while (0)

    float hm0, hm1, hc0, hc1;
    HEVAL(j0 - 1, hm0, hm1);
    HEVAL(j0, hc0, hc1);
    __half* Og = g_h1 + (size_t)b * 65536 + (size_t)(v0q + vg * 32) * 256 + c0;
#pragma unroll 8
    for (int j = j0; j < j0 + 32; j++) {
        float hp0, hp1;
        HEVAL(j + 1, hp0, hp1);
        float t0 = (hm0 + hc0 + hp0) * (1.0f / 3.0f);
        float t1 = (hm1 + hc1 + hp1) * (1.0f / 3.0f);
        *(__half2*)Og = __floats2half2_rn(t0, t1);
        Og += 256;
        hm0 = hc0; hm1 = hc1; hc0 = hp0; hc1 = hp1;
    }
#undef HEVAL
}

// ---------------------------------------------------------------------------
// MERGED persistent mma kernel: layer1 + global barrier + layer2.
// PROBE: fp16-accumulate HMMA chained per K=64 chunk (per mt-pair x nt-half
// group to bound live regs), promoted into fp32 accumulators per chunk.
// Everything else identical to the validated R16 k_mma2.
// ---------------------------------------------------------------------------
__global__ void __launch_bounds__(512, 1) k_mma2(
    const __half* __restrict__ A1, const __half* __restrict__ W,
    const float* __restrict__ b1, const float* __restrict__ b2,
    __half* __restrict__ H2, float* __restrict__ out) {
    extern __shared__ __align__(1024) char smc[];
    const uint32_t smb = s2u(smc);
    const int tid = threadIdx.x, wid = tid >> 5, lane = tid & 31;
    const int nh = blockIdx.x & 1, slot = blockIdx.x >> 1;
    const int wm = wid >> 2, wn = wid & 3;

    const uint32_t OFF_B = 98304u, OFF_S = 163840u;

    const int nt = (1024 - slot + 73) / 74;

    const int ar = tid >> 3, ac = tid & 7;
    const uint32_t swcA = (uint32_t)((ac * 16) ^ ((ar & 7) << 4));

#define ISSUE_A(AGL, BIDX, CH, BUF)                                          \
    do {                                                                     \
        const __half* _Ag = (AGL) + (size_t)(BIDX) * 65536;                  \
        uint32_t _dst = smb + (uint32_t)(BUF) * 32768u;                      \
        _Pragma("unroll") for (int _j = 0; _j < 4; _j++) {                   \
            int _row = ar + _j * 64;                                         \
            CP_ASYNC16(_dst + _row * 128 + swcA,                             \
                       _Ag + _row * 256 + (CH) * 64 + ac * 8);               \
        }                                                                    \
    } while (0)

#define ISSUE_B(BGL)                                                         \
    do {                                                                     \
        _Pragma("unroll") for (int _j = 0; _j < 8; _j++) {                   \
            int _idx = tid + _j * 512;                                       \
            int _cS = _idx >> 10, _row = (_idx >> 3) & 127, _ab = _idx & 7;  \
            uint32_t _swc = (uint32_t)((_ab * 16) ^ ((_row & 7) << 4));      \
            CP_ASYNC16(smb + OFF_B + _cS * 16384 + _row * 128 + _swc,        \
                       (BGL) + _row * 256 + _cS * 64 + _ab * 8);             \
        }                                                                    \
    } while (0)

    const int li = lane >> 3, lr = lane & 7;
    uint32_t colk[4];
#pragma unroll
    for (int kt = 0; kt < 4; kt++)
        colk[kt] = (uint32_t)((kt * 32 + (li >> 1) * 16) ^ (lr << 4));
    const uint32_t aRow = smb + (uint32_t)(wm * 64 + (li & 1) * 8 + lr) * 128;
    const uint32_t bRow = smb + OFF_B + (uint32_t)(wn * 32 + (li & 1) * 8 + lr) * 128;
    const int r = lane >> 2, l2 = (lane & 3) * 2;

    // layer-0 prologue
    ISSUE_B(W + nh * 32768);
    ISSUE_A(A1, slot, 0, 0);
    CP_COMMIT();
    ISSUE_A(A1, slot, 1, 1);
    CP_COMMIT();

    for (int lay = 0; lay < 2; lay++) {
        const __half* Agl = lay ? (const __half*)H2 : A1;
        const float* bias = lay ? b2 : b1;
        const int NC = 4 * nt;

        float bj[4][2];
#pragma unroll
        for (int nt2 = 0; nt2 < 4; nt2++) {
            int n = nh * 128 + wn * 32 + nt2 * 8 + l2;
            bj[nt2][0] = bias[n];
            bj[nt2][1] = bias[n + 1];
        }

        int g = 0;
        for (int i = 0; i < nt; i++) {
            const int b = slot + i * SLOTS;

            float acc[4][4][4];
#pragma unroll
            for (int mt = 0; mt < 4; mt++)
#pragma unroll
                for (int nt2 = 0; nt2 < 4; nt2++)
#pragma unroll
                    for (int q = 0; q < 4; q++) acc[mt][nt2][q] = 0.0f;

            for (int c = 0; c < 4; c++) {
                CP_WAIT(1);
                __syncthreads();
                int gn = g + 2;
                if (gn < NC) ISSUE_A(Agl, slot + (gn >> 2) * SLOTS, gn & 3, gn % 3);
                CP_COMMIT();

                const uint32_t aB = aRow + (uint32_t)(g % 3) * 32768u;
                const uint32_t bB = bRow + (uint32_t)c * 16384u;
                // fp16-acc chained MMA per (nt-half p, mt-pair mg)
#pragma unroll
                for (int p = 0; p < 2; p++) {
#pragma unroll
                    for (int mg = 0; mg < 2; mg++) {
                        uint32_t hacc[2][2][2];
#pragma unroll
                        for (int m2 = 0; m2 < 2; m2++)
#pragma unroll
                            for (int s = 0; s < 2; s++) {
                                hacc[m2][s][0] = 0u;
                                hacc[m2][s][1] = 0u;
                            }
#pragma unroll
                        for (int kt = 0; kt < 4; kt++) {
                            uint32_t ah[2][4], bh[4];
#pragma unroll
                            for (int m2 = 0; m2 < 2; m2++)
                                ldsm4(ah[m2][0], ah[m2][1], ah[m2][2], ah[m2][3],
                                      aB + (mg * 2 + m2) * 2048 + colk[kt]);
                            ldsm4(bh[0], bh[1], bh[2], bh[3],
                                  bB + p * 2048 + colk[kt]);
#pragma unroll
                            for (int m2 = 0; m2 < 2; m2++)
#pragma unroll
                                for (int s = 0; s < 2; s++)
                                    mma16816h(hacc[m2][s], ah[m2],
                                              bh[s], bh[2 + s]);
                        }
                        // promote chunk partials into fp32 accumulators
#pragma unroll
                        for (int m2 = 0; m2 < 2; m2++)
#pragma unroll
                            for (int s = 0; s < 2; s++) {
                                int mt = mg * 2 + m2, nn = p * 2 + s;
                                float2 lo = __half22float2(
                                    *(__half2*)&hacc[m2][s][0]);
                                float2 hi = __half22float2(
                                    *(__half2*)&hacc[m2][s][1]);
                                acc[mt][nn][0] += lo.x;
                                acc[mt][nn][1] += lo.y;
                                acc[mt][nn][2] += hi.x;
                                acc[mt][nn][3] += hi.y;
                            }
                    }
                }
                g++;
            }

            if (lay == 0) {
#pragma unroll
                for (int mt = 0; mt < 4; mt++)
#pragma unroll
                    for (int nt2 = 0; nt2 < 4; nt2++) {
                        int v = wm * 64 + mt * 16 + r;
                        uint32_t scol =
                            (uint32_t)(((wn * 32 + nt2 * 8 + l2) * 2) ^ (r << 4));
                        *(__half2*)(smc + OFF_S + v * 256 + scol) = __floats2half2_rn(
                            fsilu(acc[mt][nt2][0] + bj[nt2][0]),
                            fsilu(acc[mt][nt2][1] + bj[nt2][1]));
                        *(__half2*)(smc + OFF_S + (v + 8) * 256 + scol) =
                            __floats2half2_rn(
                                fsilu(acc[mt][nt2][2] + bj[nt2][0]),
                                fsilu(acc[mt][nt2][3] + bj[nt2][1]));
                    }
                __syncthreads();
                int np = tid & 31, vgE = tid >> 5;
                __half* Og = H2 + (size_t)b * 65536 + nh * 128 + 4 * np;
                const __half2 third = __floats2half2_rn(1.0f / 3.0f, 1.0f / 3.0f);
#pragma unroll 4
                for (int v = vgE * 16; v < vgE * 16 + 16; v++) {
                    int vm = (v + 255) & 255, vp = (v + 1) & 255;
                    uint2 ua = *(const uint2*)(smc + OFF_S + vm * 256 +
                                               ((8 * np) ^ ((vm & 7) << 4)));
                    uint2 ub = *(const uint2*)(smc + OFF_S + v * 256 +
                                               ((8 * np) ^ ((v & 7) << 4)));
                    uint2 uc = *(const uint2*)(smc + OFF_S + vp * 256 +
                                               ((8 * np) ^ ((vp & 7) << 4)));
                    __half2 r0 = __hmul2(__hadd2(__hadd2(*(__half2*)&ua.x,
                                                         *(__half2*)&ub.x),
                                                 *(__half2*)&uc.x), third);
                    __half2 r1 = __hmul2(__hadd2(__hadd2(*(__half2*)&ua.y,
                                                         *(__half2*)&ub.y),
                                                 *(__half2*)&uc.y), third);
                    uint2 res;
                    res.x = *(uint32_t*)&r0;
                    res.y = *(uint32_t*)&r1;
                    *(uint2*)(Og + (size_t)v * 256) = res;
                }
                __syncthreads();
            } else {
                float cs[4][2];
#pragma unroll
                for (int nt2 = 0; nt2 < 4; nt2++) { cs[nt2][0] = 0.0f; cs[nt2][1] = 0.0f; }
#pragma unroll
                for (int mt = 0; mt < 4; mt++)
#pragma unroll
                    for (int nt2 = 0; nt2 < 4; nt2++) {
                        cs[nt2][0] += fsilu(acc[mt][nt2][0] + bj[nt2][0]) +
                                      fsilu(acc[mt][nt2][2] + bj[nt2][0]);
                        cs[nt2][1] += fsilu(acc[mt][nt2][1] + bj[nt2][1]) +
                                      fsilu(acc[mt][nt2][3] + bj[nt2][1]);
                    }
#pragma unroll
                for (int off = 4; off <= 16; off <<= 1)
#pragma unroll
                    for (int nt2 = 0; nt2 < 4; nt2++) {
                        cs[nt2][0] += __shfl_xor_sync(0xFFFFFFFFu, cs[nt2][0], off);
                        cs[nt2][1] += __shfl_xor_sync(0xFFFFFFFFu, cs[nt2][1], off);
                    }
                float* red = (float*)(smc + OFF_S);
                if (r == 0) {
#pragma unroll
                    for (int nt2 = 0; nt2 < 4; nt2++) {
                        int n = wn * 32 + nt2 * 8 + l2;
                        red[wm * 128 + n]     = cs[nt2][0];
                        red[wm * 128 + n + 1] = cs[nt2][1];
                    }
                }
                __syncthreads();
                if (tid < 128)
                    out[b * 256 + nh * 128 + tid] =
                        (red[tid] + red[128 + tid] + red[256 + tid] + red[384 + tid]) *
                        (1.0f / 256.0f);
                __syncthreads();
            }
        }

        if (lay == 0) {
            CP_WAIT(0);
            __syncthreads();
            ISSUE_B(W + 65536 + nh * 32768);
            CP_COMMIT();
            __threadfence();
            __syncthreads();
            if (tid == 0) {
                unsigned int old = atomicAdd(&g_bar, 1u);
                unsigned int target = (old / 148u + 1u) * 148u;
                unsigned int cur;
                do {
                    asm volatile("ld.acquire.gpu.u32 %0, [%1];"
                                 : "=r"(cur) : "l"(&g_bar));
                    if (cur < target) __nanosleep(256);
                } while (cur < target);
            }
            __syncthreads();
            ISSUE_A(H2, slot, 0, 0);
            CP_COMMIT();
            ISSUE_A(H2, slot, 1, 1);
            CP_COMMIT();
        }
    }
    CP_WAIT(0);
}

// ---------------------------------------------------------------------------
extern "C" void kernel_launch(void* const* d_in, const int* in_sizes, int n_in,
                              void* d_out, int out_size) {
    const float* x  = (const float*)d_in[0];
    const float* t  = (const float*)d_in[1];
    const float* tw = (const float*)d_in[2];
    const float* tb = (const float*)d_in[3];
    const float* W0 = (const float*)d_in[4];
    const float* b0 = (const float*)d_in[5];
    const float* W1 = (const float*)d_in[6];
    const float* b1 = (const float*)d_in[7];
    const float* W2 = (const float*)d_in[8];
    const float* b2 = (const float*)d_in[9];
    float* out = (float*)d_out;

    cudaFuncSetAttribute(k_mma2, cudaFuncAttributeMaxDynamicSharedMemorySize, 229376);

    __half *h1, *h2, *w;
    cudaGetSymbolAddress((void**)&h1, g_h1);
    cudaGetSymbolAddress((void**)&h2, g_h2);
    cudaGetSymbolAddress((void**)&w,  g_W);

    k_prep<<<1408, 256>>>(W1, W2, W0, t, tw, tb, b0);
    k_layer0<<<BSZ * 4, 256>>>(x, W0);
    k_mma2<<<148, 512, 229376>>>(h1, w, b1, b2, h2, out);
}